// round 8
// baseline (speedup 1.0000x reference)
#include <cuda_runtime.h>
#include <cuda_fp16.h>
#include <cstdint>

// Problem constants (fixed shapes per reference)
#define DIMC 128
#define KC   65536
#define BC   1024
#define LC   512
#define PC   8388608
#define P4   (PC / 4)     // 2097152 float4s

// Scratch (device global — no allocation allowed)
__device__ __half g_qTh[(size_t)KC * DIMC];     // 16 MB transposed queue [K, DIM] fp16

// ---------------------------------------------------------------------------
// Kernel A (measured ~14.4us): 2048 blocks; block = 32 k x full 128 d
//   - fp16 transposed original values -> g_qTh (256B contiguous stores)
//   - new_queue = queue with cols [ptr,ptr+B) replaced by normalize(keys).T
// ---------------------------------------------------------------------------
__global__ __launch_bounds__(256) void tile_kernel(
        const float* __restrict__ queue,
        const float* __restrict__ keys,
        float* __restrict__ new_queue,
        const int* __restrict__ ptrp) {
    __shared__ float tile[32][129];

    int k0   = blockIdx.x << 5;
    int lane = threadIdx.x & 31;
    int wy   = threadIdx.x >> 5;       // warp id 0..7
    int ptr  = *ptrp;

    #pragma unroll
    for (int i = 0; i < 16; ++i) {
        int d = wy * 16 + i;
        tile[lane][d] = __ldcs(&queue[(size_t)d * KC + (k0 + lane)]);
    }
    __syncthreads();

    #pragma unroll
    for (int j = 0; j < 4; ++j) {
        int k = wy * 4 + j;
        float v0 = tile[k][4 * lane + 0];
        float v1 = tile[k][4 * lane + 1];
        float v2 = tile[k][4 * lane + 2];
        float v3 = tile[k][4 * lane + 3];
        __half2 h0 = __floats2half2_rn(v0, v1);
        __half2 h1 = __floats2half2_rn(v2, v3);
        uint2 pkt = make_uint2(*reinterpret_cast<unsigned*>(&h0),
                               *reinterpret_cast<unsigned*>(&h1));
        *reinterpret_cast<uint2*>(&g_qTh[(size_t)(k0 + k) * DIMC + 4 * lane]) = pkt;
    }

    int lo = ptr - k0;          if (lo < 0)  lo = 0;
    int hi = ptr + BC - k0;     if (hi > 32) hi = 32;
    if (lo < hi) {
        #pragma unroll
        for (int j = 0; j < 4; ++j) {
            int k = wy * 4 + j;
            if (k >= lo && k < hi) {
                int r = k0 + k - ptr;               // key row
                float4 v = reinterpret_cast<const float4*>(keys + (size_t)r * DIMC)[lane];
                float s = v.x * v.x + v.y * v.y + v.z * v.z + v.w * v.w;
                #pragma unroll
                for (int o = 16; o > 0; o >>= 1) s += __shfl_xor_sync(0xFFFFFFFFu, s, o);
                float inv = 1.0f / sqrtf(s);
                tile[k][4 * lane + 0] = v.x * inv;
                tile[k][4 * lane + 1] = v.y * inv;
                tile[k][4 * lane + 2] = v.z * inv;
                tile[k][4 * lane + 3] = v.w * inv;
            }
        }
    }
    __syncthreads();

    #pragma unroll
    for (int i = 0; i < 16; ++i) {
        int d = wy * 16 + i;
        __stcs(&new_queue[(size_t)d * KC + (k0 + lane)], tile[lane][d]);
    }
}

// ---------------------------------------------------------------------------
// Kernel B: 1024 blocks x 512 threads, WARP-SPECIALIZED.
//   warps 0-7  : logits gather for batch row b (R3's proven loop, unchanged)
//   warps 8-15 : this block's 1/1024 slice of the param EMA (2048 float4s,
//                unrolled 4-deep -> 8 DRAM loads in flight per thread group)
// Both classes co-resident on every SM -> DRAM stream hides under L2 gather.
// ---------------------------------------------------------------------------
__global__ __launch_bounds__(512) void logits_ema_kernel(
        const float* __restrict__ q,
        const int* __restrict__ sidx,
        const float* __restrict__ pq,
        const float* __restrict__ pk,
        float* __restrict__ logits,
        float* __restrict__ labels,
        float* __restrict__ new_pk) {
    __shared__ float4 qs4[32];
    int tid = threadIdx.x;
    int b   = blockIdx.x;

    if (tid < 32) {
        float4 v = reinterpret_cast<const float4*>(q + (size_t)b * DIMC)[tid];
        float s = v.x * v.x + v.y * v.y + v.z * v.z + v.w * v.w;
        #pragma unroll
        for (int o = 16; o > 0; o >>= 1) s += __shfl_xor_sync(0xFFFFFFFFu, s, o);
        float inv = 1.0f / sqrtf(s);
        qs4[tid] = make_float4(v.x * inv, v.y * inv, v.z * inv, v.w * inv);
    }
    if (tid == 0) labels[b] = 0.0f;
    __syncthreads();

    if (tid < 256) {
        // ---- gather warps (0-7): R3 inner loop verbatim ----
        int lane    = tid & 31;
        int warp    = tid >> 5;      // 0..7
        int half_id = lane >> 4;     // which of the 2 samples this lane serves
        int subl    = lane & 15;     // position within the 16-lane group

        float4 qa = qs4[subl * 2];
        float4 qb = qs4[subl * 2 + 1];

        const int* row = sidx + (size_t)b * LC;
        float* lrow = logits + (size_t)b * LC;

        #pragma unroll 4
        for (int l = warp * 2; l < LC; l += 16) {
            int idx = row[l + half_id];
            int4 pkt = reinterpret_cast<const int4*>(g_qTh + (size_t)idx * DIMC)[subl];
            float2 f0 = __half22float2(*reinterpret_cast<__half2*>(&pkt.x));
            float2 f1 = __half22float2(*reinterpret_cast<__half2*>(&pkt.y));
            float2 f2 = __half22float2(*reinterpret_cast<__half2*>(&pkt.z));
            float2 f3 = __half22float2(*reinterpret_cast<__half2*>(&pkt.w));
            float s = f0.x * qa.x + f0.y * qa.y + f1.x * qa.z + f1.y * qa.w
                    + f2.x * qb.x + f2.y * qb.y + f3.x * qb.z + f3.y * qb.w;
            #pragma unroll
            for (int o = 8; o > 0; o >>= 1)
                s += __shfl_xor_sync(0xFFFFFFFFu, s, o);
            if (subl == 0)
                lrow[l + half_id] = s * (1.0f / 0.09f);
        }
    } else {
        // ---- EMA warps (8-15): 2048 float4s per block, 4-deep unroll ----
        int eid  = tid - 256;                 // 0..255
        int base = b * 2048 + eid;
        const float4* pq4  = reinterpret_cast<const float4*>(pq);
        const float4* pk4  = reinterpret_cast<const float4*>(pk);
        float4*       out4 = reinterpret_cast<float4*>(new_pk);

        #pragma unroll
        for (int g = 0; g < 2; ++g) {
            int i0 = base + (g * 4 + 0) * 256;
            int i1 = base + (g * 4 + 1) * 256;
            int i2 = base + (g * 4 + 2) * 256;
            int i3 = base + (g * 4 + 3) * 256;
            float4 a0 = __ldcs(pq4 + i0);
            float4 b0 = __ldcs(pk4 + i0);
            float4 a1 = __ldcs(pq4 + i1);
            float4 b1 = __ldcs(pk4 + i1);
            float4 a2 = __ldcs(pq4 + i2);
            float4 b2 = __ldcs(pk4 + i2);
            float4 a3 = __ldcs(pq4 + i3);
            float4 b3 = __ldcs(pk4 + i3);
            float4 r0 = make_float4(b0.x*0.7f+a0.x*0.3f, b0.y*0.7f+a0.y*0.3f,
                                    b0.z*0.7f+a0.z*0.3f, b0.w*0.7f+a0.w*0.3f);
            float4 r1 = make_float4(b1.x*0.7f+a1.x*0.3f, b1.y*0.7f+a1.y*0.3f,
                                    b1.z*0.7f+a1.z*0.3f, b1.w*0.7f+a1.w*0.3f);
            float4 r2 = make_float4(b2.x*0.7f+a2.x*0.3f, b2.y*0.7f+a2.y*0.3f,
                                    b2.z*0.7f+a2.z*0.3f, b2.w*0.7f+a2.w*0.3f);
            float4 r3 = make_float4(b3.x*0.7f+a3.x*0.3f, b3.y*0.7f+a3.y*0.3f,
                                    b3.z*0.7f+a3.z*0.3f, b3.w*0.7f+a3.w*0.3f);
            __stcs(out4 + i0, r0);
            __stcs(out4 + i1, r1);
            __stcs(out4 + i2, r2);
            __stcs(out4 + i3, r3);
        }
    }
}

// ---------------------------------------------------------------------------
extern "C" void kernel_launch(void* const* d_in, const int* in_sizes, int n_in,
                              void* d_out, int out_size) {
    const float* q        = (const float*)d_in[0];
    const float* queue    = (const float*)d_in[1];
    const float* keys     = (const float*)d_in[2];
    const float* param_q  = (const float*)d_in[3];
    const float* param_k  = (const float*)d_in[4];
    const int*   sidx     = (const int*)  d_in[5];
    const int*   ptr      = (const int*)  d_in[6];

    float* out       = (float*)d_out;
    float* logits    = out;                            // B*L = 524288
    float* labels    = logits + (size_t)BC * LC;       // 1024
    float* new_queue = labels + BC;                    // DIM*K = 8388608
    float* new_pk    = new_queue + (size_t)DIMC * KC;  // P = 8388608

    // Kernel A: fp16 transpose + fp32 enqueue/copy (one read of queue)
    tile_kernel<<<2048, 256>>>(queue, keys, new_queue, ptr);

    // Kernel B: warp-specialized logits gather + EMA + labels
    logits_ema_kernel<<<BC, 512>>>(q, sidx, param_q, param_k,
                                   logits, labels, new_pk);
}

// round 10
// speedup vs baseline: 1.4382x; 1.4382x over previous
#include <cuda_runtime.h>
#include <cuda_fp16.h>
#include <cstdint>

// Problem constants (fixed shapes per reference)
#define DIMC 128
#define KC   65536
#define BC   1024
#define LC   512
#define PC   8388608

// Scratch (device globals — no allocation allowed)
__device__ __half g_qTh[(size_t)KC * DIMC];   // 16 MB transposed queue [K, DIM] fp16
__device__ float  g_keysN[BC * DIMC];         // normalized keys (0.5 MB)

// ---------------------------------------------------------------------------
// Kernel A: 2048 transpose blocks + 128 key-normalize blocks.
//   transpose block: 32 k-cols x 128 dims of queue -> fp16 g_qTh (256B rows)
//   keyN block: 8 warps, one key row per warp -> g_keysN (128*8 = 1024 rows)
// ---------------------------------------------------------------------------
__global__ __launch_bounds__(256) void prep_kernel(
        const float* __restrict__ queue,
        const float* __restrict__ keys) {
    if (blockIdx.x < 2048) {
        __shared__ float tile[32][129];
        int k0   = blockIdx.x << 5;
        int lane = threadIdx.x & 31;
        int wy   = threadIdx.x >> 5;       // warp id 0..7

        #pragma unroll
        for (int i = 0; i < 16; ++i) {
            int d = wy * 16 + i;
            tile[lane][d] = __ldg(&queue[(size_t)d * KC + (k0 + lane)]);
        }
        __syncthreads();

        #pragma unroll
        for (int j = 0; j < 4; ++j) {
            int k = wy * 4 + j;
            float v0 = tile[k][4 * lane + 0];
            float v1 = tile[k][4 * lane + 1];
            float v2 = tile[k][4 * lane + 2];
            float v3 = tile[k][4 * lane + 3];
            __half2 h0 = __floats2half2_rn(v0, v1);
            __half2 h1 = __floats2half2_rn(v2, v3);
            uint2 pkt = make_uint2(*reinterpret_cast<unsigned*>(&h0),
                                   *reinterpret_cast<unsigned*>(&h1));
            *reinterpret_cast<uint2*>(&g_qTh[(size_t)(k0 + k) * DIMC + 4 * lane]) = pkt;
        }
    } else {
        // key normalization: one warp per key row, 128 blocks x 8 warps = 1024
        int gw   = (blockIdx.x - 2048) * 8 + (threadIdx.x >> 5);  // 0..1023
        int lane = threadIdx.x & 31;
        float4 v = reinterpret_cast<const float4*>(keys + (size_t)gw * DIMC)[lane];
        float s = v.x * v.x + v.y * v.y + v.z * v.z + v.w * v.w;
        #pragma unroll
        for (int o = 16; o > 0; o >>= 1) s += __shfl_xor_sync(0xFFFFFFFFu, s, o);
        float inv = 1.0f / sqrtf(s);
        reinterpret_cast<float4*>(g_keysN + (size_t)gw * DIMC)[lane] =
            make_float4(v.x * inv, v.y * inv, v.z * inv, v.w * inv);
    }
}

// ---------------------------------------------------------------------------
// Kernel B: block pool, ordered longest-first.
//   bid [0, 1024)        : logits gather for batch row b (R3 proven loop)
//   bid [1024, 3072)     : queue copy + enqueue (1024 float4s per block)
//   bid [3072, 11264)    : EMA stream (256 float4s per block)
// ---------------------------------------------------------------------------
__global__ __launch_bounds__(256) void pool_kernel(
        const float* __restrict__ q,
        const int* __restrict__ sidx,
        const float* __restrict__ queue,
        const float* __restrict__ pq,
        const float* __restrict__ pk,
        const int* __restrict__ ptrp,
        float* __restrict__ logits,
        float* __restrict__ labels,
        float* __restrict__ new_queue,
        float* __restrict__ new_pk) {
    int bid = blockIdx.x;

    if (bid < BC) {
        // ---- logits gather (R3 verbatim) ----
        int b = bid;
        __shared__ float4 qs4[32];
        int tid = threadIdx.x;
        if (tid < 32) {
            float4 v = reinterpret_cast<const float4*>(q + (size_t)b * DIMC)[tid];
            float s = v.x * v.x + v.y * v.y + v.z * v.z + v.w * v.w;
            #pragma unroll
            for (int o = 16; o > 0; o >>= 1) s += __shfl_xor_sync(0xFFFFFFFFu, s, o);
            float inv = 1.0f / sqrtf(s);
            qs4[tid] = make_float4(v.x * inv, v.y * inv, v.z * inv, v.w * inv);
        }
        if (tid == 0) labels[b] = 0.0f;
        __syncthreads();

        int lane    = tid & 31;
        int warp    = tid >> 5;
        int half_id = lane >> 4;
        int subl    = lane & 15;

        float4 qa = qs4[subl * 2];
        float4 qb = qs4[subl * 2 + 1];

        const int* row = sidx + (size_t)b * LC;
        float* lrow = logits + (size_t)b * LC;

        #pragma unroll 4
        for (int l = warp * 2; l < LC; l += 16) {
            int idx = row[l + half_id];
            int4 pkt = reinterpret_cast<const int4*>(g_qTh + (size_t)idx * DIMC)[subl];
            float2 f0 = __half22float2(*reinterpret_cast<__half2*>(&pkt.x));
            float2 f1 = __half22float2(*reinterpret_cast<__half2*>(&pkt.y));
            float2 f2 = __half22float2(*reinterpret_cast<__half2*>(&pkt.z));
            float2 f3 = __half22float2(*reinterpret_cast<__half2*>(&pkt.w));
            float s = f0.x * qa.x + f0.y * qa.y + f1.x * qa.z + f1.y * qa.w
                    + f2.x * qb.x + f2.y * qb.y + f3.x * qb.z + f3.y * qb.w;
            #pragma unroll
            for (int o = 8; o > 0; o >>= 1)
                s += __shfl_xor_sync(0xFFFFFFFFu, s, o);
            if (subl == 0)
                lrow[l + half_id] = s * (1.0f / 0.09f);
        }
    } else if (bid < 3072) {
        // ---- queue copy + enqueue: 1024 float4s (4 per thread) ----
        int ptr = *ptrp;
        int base = (bid - BC) * 1024 + (int)threadIdx.x;   // float4 index base
        #pragma unroll
        for (int g = 0; g < 4; ++g) {
            int i = base + g * 256;                        // float4 index
            float4 v = __ldg(reinterpret_cast<const float4*>(queue) + i);
            int e = i << 2;
            int d = e >> 16;          // / K
            int k = e & (KC - 1);     // % K
            float* c = &v.x;
            #pragma unroll
            for (int j = 0; j < 4; ++j) {
                int r = k + j - ptr;
                if ((unsigned)r < (unsigned)BC)
                    c[j] = g_keysN[(size_t)r * DIMC + d];
            }
            __stcs(reinterpret_cast<float4*>(new_queue) + i, v);
        }
    } else {
        // ---- EMA: 256 float4s per block (R3 proven) ----
        int i = (bid - 3072) * 256 + (int)threadIdx.x;
        float4 a  = __ldcs(reinterpret_cast<const float4*>(pq) + i);
        float4 b4 = __ldcs(reinterpret_cast<const float4*>(pk) + i);
        float4 r = make_float4(b4.x * 0.7f + a.x * 0.3f,
                               b4.y * 0.7f + a.y * 0.3f,
                               b4.z * 0.7f + a.z * 0.3f,
                               b4.w * 0.7f + a.w * 0.3f);
        __stcs(reinterpret_cast<float4*>(new_pk) + i, r);
    }
}

// ---------------------------------------------------------------------------
extern "C" void kernel_launch(void* const* d_in, const int* in_sizes, int n_in,
                              void* d_out, int out_size) {
    const float* q        = (const float*)d_in[0];
    const float* queue    = (const float*)d_in[1];
    const float* keys     = (const float*)d_in[2];
    const float* param_q  = (const float*)d_in[3];
    const float* param_k  = (const float*)d_in[4];
    const int*   sidx     = (const int*)  d_in[5];
    const int*   ptr      = (const int*)  d_in[6];

    float* out       = (float*)d_out;
    float* logits    = out;                            // B*L = 524288
    float* labels    = logits + (size_t)BC * LC;       // 1024
    float* new_queue = labels + BC;                    // DIM*K = 8388608
    float* new_pk    = new_queue + (size_t)DIMC * KC;  // P = 8388608

    // Kernel A: fp16 transpose + key normalization (1024 rows -> 128 blocks)
    prep_kernel<<<2048 + 128, 256>>>(queue, keys);

    // Kernel B: block pool — gather, copy+enqueue, EMA (longest-first order)
    pool_kernel<<<1024 + 2048 + PC / 1024, 256>>>(
        q, sidx, queue, param_q, param_k, ptr,
        logits, labels, new_queue, new_pk);
}